// round 15
// baseline (speedup 1.0000x reference)
#include <cuda_runtime.h>
#include <cuda_fp16.h>
#include <math.h>

#define BB 4
#define CC 64
#define WW 128
#define HH 128
#define KK 9
#define OCC 64
#define GG 16
#define EPSV 1e-5f

// Scratch (static device globals — no allocation allowed)
// Paired fp16 NHWC: g_fTh2[((b*W+y)*H+x)*128 + c*2 + {0,1}] = (f[y][x][c], f[y][min(x+1,127)][c])
__device__ __align__(16) unsigned short g_fTh2[BB * WW * HH * 128];
__device__ __align__(16) unsigned int g_Wt2[KK * CC * (OCC / 2)]; // [k][c][oc/2] half2
__device__ __align__(16) uint4 g_par[BB * KK * WW * HH];    // {base, dy, w01, w23}
__device__ float g_stats[BB * GG * 2];                      // (sum, sumsq)

__device__ __forceinline__ unsigned int s2u(const void* p) {
    unsigned int a;
    asm("{ .reg .u64 t; cvta.to.shared.u64 t, %1; cvt.u32.u64 %0, t; }"
        : "=r"(a) : "l"(p));
    return a;
}

#define LDSM_X4(r0, r1, r2, r3, addr) \
    asm volatile("ldmatrix.sync.aligned.m8n8.x4.shared.b16 {%0,%1,%2,%3}, [%4];" \
                 : "=r"(r0), "=r"(r1), "=r"(r2), "=r"(r3) : "r"(addr))
#define LDSM_X4_T(r0, r1, r2, r3, addr) \
    asm volatile("ldmatrix.sync.aligned.m8n8.x4.trans.shared.b16 {%0,%1,%2,%3}, [%4];" \
                 : "=r"(r0), "=r"(r1), "=r"(r2), "=r"(r3) : "r"(addr))

// ---------------------------------------------------------------------------
// Kernel A: offset conv (9 of 18 oc) + BN + tanh + partial cumsum ->
// packed bilinear params. Block 256: group g = tid>>7 accumulates channels
// [g*32, g*32+32) over 4 chunks; partials combined via smem. Fused: paired
// fp16 NHWC copy of f, weight packing (blocks 0..71), stat zeroing (block 0).
// Dynamic smem layout (floats):
//   [0, 6912)        w_s  [c][tap*12+k]
//   [6912, 13056)    rows [g][dy][c][128]  (aliased by accbuf [9][128] at end)
// ---------------------------------------------------------------------------
__global__ void __launch_bounds__(256, 3) offset_kernel(
    const float* __restrict__ f, const float* __restrict__ offset_w,
    const float* __restrict__ offset_b, const float* __restrict__ bn_gamma,
    const float* __restrict__ bn_beta, const float* __restrict__ bn_mean,
    const float* __restrict__ bn_var, const float* __restrict__ conv_w) {
    extern __shared__ float smf[];
    float* w_s = smf;                       // 6912 floats
    float* rowsb = smf + 6912;              // 6144 floats: [g][dy][c][128]

    const int bw = blockIdx.x;
    const int b = bw >> 7, w = bw & 127;
    const int tid = threadIdx.x;
    const int grp = tid >> 7;
    const int h = tid & 127;

    // fused weight packing: conv_w [oc][c][k] -> g_Wt2 [k][c][oc] half pairs
    if (bw < 72) {
        int i = bw * 256 + tid;              // 72*256 = 18432 exactly
        int k = i / 2048;
        int r = i & 2047;
        int c = r >> 5, oc2 = (r & 31) << 1;
        float w0 = conv_w[(((oc2 << 6) + c) * KK) + k];
        float w1 = conv_w[((((oc2 + 1) << 6) + c) * KK) + k];
        __half2 p = __floats2half2_rn(w0, w1);
        g_Wt2[i] = *(unsigned int*)&p;
    }
    if (bw == 0 && tid < BB * GG * 2) g_stats[tid] = 0.f;

    for (int i = tid; i < 9 * 64 * 9; i += 256) {
        int k = i / 576;
        int r = i - k * 576;
        int c = r / 9, tap = r - (r / 9) * 9;
        w_s[c * 108 + tap * 12 + k] = offset_w[(k * 64 + c) * 9 + tap];
    }

    float acc[9];
    #pragma unroll
    for (int k = 0; k < 9; k++) acc[k] = 0.f;

    const int hn = (h < 127) ? h + 1 : 127;
    float* rows = rowsb + grp * 3072;       // [dy][c][128]

    #pragma unroll 1
    for (int ci = 0; ci < 4; ci++) {
        const int cc = (grp << 5) + (ci << 3);
        __syncthreads();
        // load 3 rows x 8 channels for this group's chunk (24 elems/thread)
        for (int i = h; i < 3 * 8 * 128; i += 128) {
            int dy = i / 1024;
            int rem = i - dy * 1024;
            int c = rem >> 7, hh = rem & 127;
            int wr = w + dy - 1;
            float v = 0.f;
            if (wr >= 0 && wr < WW) v = f[((b * CC + cc + c) * WW + wr) * HH + hh];
            rows[dy * 1024 + (c << 7) + hh] = v;
        }
        __syncthreads();
        // fused paired transpose: (f[w][h][c], f[w][h+1][c]) for 8 channels
        {
            __half2 hp[8];
            #pragma unroll
            for (int c = 0; c < 8; c++)
                hp[c] = __floats2half2_rn(rows[1024 + (c << 7) + h],
                                          rows[1024 + (c << 7) + hn]);
            unsigned short* dst = &g_fTh2[((b * WW + w) * HH + h) * 128 + cc * 2];
            *(uint4*)dst = *(uint4*)hp;
            *(uint4*)(dst + 8) = *(uint4*)(hp + 4);
        }
        #pragma unroll
        for (int c = 0; c < 8; c++) {
            const float* wb = &w_s[(cc + c) * 108];
            #pragma unroll
            for (int dy = 0; dy < 3; dy++) {
                const float* rp = rows + dy * 1024 + (c << 7);
                float vm = (h > 0) ? rp[h - 1] : 0.f;
                float vc = rp[h];
                float vp = (h < 127) ? rp[h + 1] : 0.f;
                #pragma unroll
                for (int dx = 0; dx < 3; dx++) {
                    float v = (dx == 0) ? vm : ((dx == 1) ? vc : vp);
                    const float* wp = wb + (dy * 3 + dx) * 12;
                    float4 w0 = *(const float4*)(wp);
                    float4 w1 = *(const float4*)(wp + 4);
                    float w8 = wp[8];
                    acc[0] = fmaf(v, w0.x, acc[0]);
                    acc[1] = fmaf(v, w0.y, acc[1]);
                    acc[2] = fmaf(v, w0.z, acc[2]);
                    acc[3] = fmaf(v, w0.w, acc[3]);
                    acc[4] = fmaf(v, w1.x, acc[4]);
                    acc[5] = fmaf(v, w1.y, acc[5]);
                    acc[6] = fmaf(v, w1.z, acc[6]);
                    acc[7] = fmaf(v, w1.w, acc[7]);
                    acc[8] = fmaf(v, w8, acc[8]);
                }
            }
        }
    }

    // combine group partials: group 1 -> smem (aliases rows), group 0 adds
    __syncthreads();
    float* accbuf = rowsb;                  // 9*128 floats
    if (grp == 1) {
        #pragma unroll
        for (int k = 0; k < 9; k++) accbuf[(k << 7) + h] = acc[k];
    }
    __syncthreads();
    if (grp == 1) return;
    #pragma unroll
    for (int k = 0; k < 9; k++) acc[k] += accbuf[(k << 7) + h];

    float off[9];
    #pragma unroll
    for (int k = 0; k < 9; k++) {
        float sc = bn_gamma[k] * rsqrtf(bn_var[k] + EPSV);
        off[k] = tanhf((acc[k] + offset_b[k] - bn_mean[k]) * sc + bn_beta[k]);
    }
    float cum[9];
    cum[4] = 0.f;
    cum[0] = off[0];
    cum[8] = off[8];
    cum[5] = off[5];
    cum[6] = cum[5] + off[6];
    cum[7] = cum[6] + off[7];
    cum[3] = off[3];
    cum[2] = cum[3] + off[2];
    cum[1] = cum[2] + off[1];

    #pragma unroll
    for (int k = 0; k < 9; k++) {
        float ys = (float)w + cum[k];
        float xs = (float)h + (-5.0f + 1.125f * (float)k);   // linspace(-5,4,9)
        int y0 = (int)floorf(ys);
        y0 = max(0, min(y0, WW - 1));
        int y1 = min(y0 + 1, WW - 1);
        int x0 = (int)floorf(xs);
        x0 = max(0, min(x0, HH - 1));
        int x1 = min(x0 + 1, HH - 1);
        float wy1 = (float)y1 - ys;
        float wy0 = ys - (float)y0;
        float wx1 = (float)x1 - xs;
        float wx0 = xs - (float)x0;
        uint4 pr;
        pr.x = (unsigned int)((((b * WW + y0) * HH) + x0) * 128);  // halves
        pr.y = (unsigned int)((y1 - y0) * 16384);                  // dy in halves
        __half2 w01 = __floats2half2_rn(wy1 * wx1, wy1 * wx0);
        __half2 w23 = __floats2half2_rn(wy0 * wx1, wy0 * wx0);
        pr.z = *(unsigned int*)&w01;
        pr.w = *(unsigned int*)&w23;
        g_par[((b * KK + k) * WW + w) * HH + h] = pr;
    }
}

// ---------------------------------------------------------------------------
// Kernel B: bilinear gather (paired fp16 source: ONE LDG.128 per y-row gives
// both x corners for 4 channels) + FP16 tensor-core GEMM (ldmatrix) + GN
// partial sums. grid (B*W), block 256 (8 warps), occ 4, double-buffered.
// smem bytes: [0,9216) wtB_0 | [9216,18432) wtB_1
//             [18432,36864) dks_0 [h][c] pitch 72 halves | [36864,55296) dks_1
// epilogue zbuf (64*132 floats) aliases the front, after a sync.
// ---------------------------------------------------------------------------
#define DKPH 72
#define ZBP 132

__global__ void __launch_bounds__(256, 4) main_kernel(
    const float* __restrict__ conv_b, float* __restrict__ out) {
    extern __shared__ char smc[];
    float* zbuf = (float*)smc;                         // epilogue: 64*132 floats

    const int bw = blockIdx.x;
    const int b = bw >> 7, w = bw & 127;
    const int tid = threadIdx.x;
    const int lane = tid & 31;
    const int wid = tid >> 5;
    const int g = lane >> 2, t = lane & 3;
    const int h0 = (wid & 3) << 5;        // m32 tile
    const int n0 = (wid >> 2) << 5;       // n32 tile

    const unsigned int smem_u32 = s2u(smc);

    // ldmatrix per-lane address offsets (bytes); mat = lane>>3
    const int mat = lane >> 3;
    const int mrow = ((mat & 1) << 3) | (lane & 7);
    const int mcol = (mat >> 1) << 3;                  // halves
    const int aoff = (h0 + mrow) * 144 + mcol * 2;     // A: dks rows
    const int boff = mrow * 144 + (n0 + mcol) * 2;     // B: wt k-rows

    float acc[2][4][4];
    #pragma unroll
    for (int mi = 0; mi < 2; mi++)
        #pragma unroll
        for (int nj = 0; nj < 4; nj++)
            #pragma unroll
            for (int j = 0; j < 4; j++) acc[mi][nj][j] = 0.f;

    const int cq8 = (tid & 15) << 3;       // paired-half offset (4 channels)
    const int cq4 = (tid & 15) << 2;       // dks half offset (4 channels)

    for (int k = 0; k < KK; k++) {
        const int par = k & 1;
        unsigned int* wt2 = (unsigned int*)(smc + par * 9216);
        unsigned short* dksh = (unsigned short*)(smc + 18432 + par * 18432);
        const unsigned int wt32 = smem_u32 + par * 9216;
        const unsigned int dk32 = smem_u32 + 18432 + par * 18432;

        // stage weights: exactly 512 uint4s; dst row pitch 9 uint4 (144 B)
        #pragma unroll
        for (int j = 0; j < 2; j++) {
            int i4 = tid + (j << 8);                 // 0..511
            int row = i4 >> 3, col = i4 & 7;
            *((uint4*)wt2 + row * 9 + col) = ((const uint4*)g_Wt2)[(k << 9) + i4];
        }
        // gather -> dksh[h][c] fp16 (fp32 interpolation, paired corners)
        const int pbase = ((b * KK + k) * WW + w) * HH;
        #pragma unroll
        for (int pass = 0; pass < 8; pass++) {
            const int hg = (tid >> 4) + (pass << 4);
            const uint4 pr = __ldg(&g_par[pbase + hg]);
            const int base = (int)pr.x + cq8;
            const int dy = (int)pr.y;
            const __half2 hw01 = *(const __half2*)&pr.z;
            const __half2 hw23 = *(const __half2*)&pr.w;
            const float w00 = __low2float(hw01), w01f = __high2float(hw01);
            const float w10 = __low2float(hw23), w11f = __high2float(hw23);
            // y0 row: 4 channels x (x0,x1) pairs in one LDG.128
            uint4 A0 = *(const uint4*)&g_fTh2[base];
            uint4 A1 = *(const uint4*)&g_fTh2[base + dy];
            float2 p0 = __half22float2(*(__half2*)&A0.x);   // c0: (lo=x0, hi=x1)
            float2 p1 = __half22float2(*(__half2*)&A0.y);
            float2 p2 = __half22float2(*(__half2*)&A0.z);
            float2 p3 = __half22float2(*(__half2*)&A0.w);
            float rx = p0.x * w00, ry = p1.x * w00, rz = p2.x * w00, rw = p3.x * w00;
            rx = fmaf(p0.y, w01f, rx); ry = fmaf(p1.y, w01f, ry);
            rz = fmaf(p2.y, w01f, rz); rw = fmaf(p3.y, w01f, rw);
            p0 = __half22float2(*(__half2*)&A1.x);
            p1 = __half22float2(*(__half2*)&A1.y);
            p2 = __half22float2(*(__half2*)&A1.z);
            p3 = __half22float2(*(__half2*)&A1.w);
            rx = fmaf(p0.x, w10, rx); ry = fmaf(p1.x, w10, ry);
            rz = fmaf(p2.x, w10, rz); rw = fmaf(p3.x, w10, rw);
            rx = fmaf(p0.y, w11f, rx); ry = fmaf(p1.y, w11f, ry);
            rz = fmaf(p2.y, w11f, rz); rw = fmaf(p3.y, w11f, rw);
            __half2 q0 = __floats2half2_rn(rx, ry);   // low = even c
            __half2 q1 = __floats2half2_rn(rz, rw);
            uint2 pk;
            pk.x = *(unsigned int*)&q0;
            pk.y = *(unsigned int*)&q1;
            *(uint2*)&dksh[hg * DKPH + cq4] = pk;
        }
        __syncthreads();
        // MMA: warp tile m32 x n32, K=64 halves in 4 k16 chunks, ldmatrix frags
        #pragma unroll
        for (int kc = 0; kc < 4; kc++) {
            unsigned int a0[4], a1[4], bb0[4], bb1[4];
            const unsigned int aa = dk32 + aoff + kc * 32;
            LDSM_X4(a0[0], a0[1], a0[2], a0[3], aa);
            LDSM_X4(a1[0], a1[1], a1[2], a1[3], aa + 16 * 144);
            const unsigned int ba = wt32 + boff + kc * 2304;   // 16 k-rows
            LDSM_X4_T(bb0[0], bb0[1], bb0[2], bb0[3], ba);
            LDSM_X4_T(bb1[0], bb1[1], bb1[2], bb1[3], ba + 32);
            #pragma unroll
            for (int nj = 0; nj < 4; nj++) {
                const unsigned int b0 = (nj < 2) ? bb0[(nj & 1) << 1] : bb1[(nj & 1) << 1];
                const unsigned int b1 = (nj < 2) ? bb0[((nj & 1) << 1) + 1]
                                                 : bb1[((nj & 1) << 1) + 1];
                #pragma unroll
                for (int mi = 0; mi < 2; mi++) {
                    unsigned int* a = mi ? a1 : a0;
                    asm("mma.sync.aligned.m16n8k16.row.col.f32.f16.f16.f32 "
                        "{%0,%1,%2,%3}, {%4,%5,%6,%7}, {%8,%9}, {%0,%1,%2,%3};"
                        : "+f"(acc[mi][nj][0]), "+f"(acc[mi][nj][1]),
                          "+f"(acc[mi][nj][2]), "+f"(acc[mi][nj][3])
                        : "r"(a[0]), "r"(a[1]), "r"(a[2]), "r"(a[3]),
                          "r"(b0), "r"(b1));
                }
            }
        }
    }

    // epilogue: fragments -> zbuf[oc][h] -> coalesced out + GN stats
    __syncthreads();     // all MMA reads of dks/wt2 done before aliasing as zbuf
    #pragma unroll
    for (int mi = 0; mi < 2; mi++) {
        #pragma unroll
        for (int nj = 0; nj < 4; nj++) {
            const int oc = n0 + (nj << 3) + (t << 1);
            const int hh = h0 + (mi << 4) + g;
            zbuf[oc * ZBP + hh] = acc[mi][nj][0];
            zbuf[(oc + 1) * ZBP + hh] = acc[mi][nj][1];
            zbuf[oc * ZBP + hh + 8] = acc[mi][nj][2];
            zbuf[(oc + 1) * ZBP + hh + 8] = acc[mi][nj][3];
        }
    }
    __syncthreads();
    const int oc = tid >> 2;
    const int hq = (tid & 3) << 5;
    const float bias = conv_b[oc];
    float s1 = 0.f, s2 = 0.f;
    float* op = out + ((b * OCC + oc) * WW + w) * HH + hq;
    #pragma unroll
    for (int j = 0; j < 8; j++) {
        float4 v = *(float4*)&zbuf[oc * ZBP + hq + (j << 2)];
        v.x += bias; v.y += bias; v.z += bias; v.w += bias;
        s1 += v.x + v.y + v.z + v.w;
        s2 += v.x * v.x + v.y * v.y + v.z * v.z + v.w * v.w;
        *(float4*)&op[j << 2] = v;
    }
    #pragma unroll
    for (int m = 1; m <= 8; m <<= 1) {
        s1 += __shfl_xor_sync(0xffffffffu, s1, m);
        s2 += __shfl_xor_sync(0xffffffffu, s2, m);
    }
    if ((lane & 15) == 0) {
        const int grp = oc >> 2;
        atomicAdd(&g_stats[(b * GG + grp) * 2 + 0], s1);
        atomicAdd(&g_stats[(b * GG + grp) * 2 + 1], s2);
    }
}

// ---------------------------------------------------------------------------
// Kernel C: GroupNorm finalize + ReLU (in place on out)
// ---------------------------------------------------------------------------
__global__ void __launch_bounds__(256) gn_kernel(float* __restrict__ out,
                                                 const float* __restrict__ gn_gamma,
                                                 const float* __restrict__ gn_beta) {
    const int idx = blockIdx.x * 256 + threadIdx.x;
    const int i4 = idx << 2;
    const int oc = (i4 >> 14) & 63;
    const int b = i4 >> 20;
    const int g = oc >> 2;
    const float inv = 1.0f / 65536.0f;
    float s1 = g_stats[(b * GG + g) * 2 + 0];
    float s2 = g_stats[(b * GG + g) * 2 + 1];
    float mean = s1 * inv;
    float var = s2 * inv - mean * mean;
    float sc = gn_gamma[oc] * rsqrtf(var + EPSV);
    float sh = gn_beta[oc] - mean * sc;
    float4* o4 = (float4*)out;
    float4 v = o4[idx];
    v.x = fmaxf(v.x * sc + sh, 0.f);
    v.y = fmaxf(v.y * sc + sh, 0.f);
    v.z = fmaxf(v.z * sc + sh, 0.f);
    v.w = fmaxf(v.w * sc + sh, 0.f);
    o4[idx] = v;
}

// ---------------------------------------------------------------------------
extern "C" void kernel_launch(void* const* d_in, const int* in_sizes, int n_in,
                              void* d_out, int out_size) {
    const float* f        = (const float*)d_in[0];
    const float* offset_w = (const float*)d_in[1];
    const float* offset_b = (const float*)d_in[2];
    const float* bn_gamma = (const float*)d_in[3];
    const float* bn_beta  = (const float*)d_in[4];
    const float* bn_mean  = (const float*)d_in[5];
    const float* bn_var   = (const float*)d_in[6];
    const float* conv_w   = (const float*)d_in[7];
    const float* conv_b   = (const float*)d_in[8];
    const float* gn_gamma = (const float*)d_in[9];
    const float* gn_beta  = (const float*)d_in[10];
    float* out = (float*)d_out;

    const int off_smem = (6912 + 6144) * 4;   // 52224 bytes
    cudaFuncSetAttribute(offset_kernel, cudaFuncAttributeMaxDynamicSharedMemorySize,
                         off_smem);
    const int main_smem = 55296;   // 2x wtB (9216) + 2x dks (18432)
    cudaFuncSetAttribute(main_kernel, cudaFuncAttributeMaxDynamicSharedMemorySize,
                         main_smem);

    offset_kernel<<<BB * WW, 256, off_smem>>>(f, offset_w, offset_b, bn_gamma,
                                              bn_beta, bn_mean, bn_var, conv_w);

    main_kernel<<<BB * WW, 256, main_smem>>>(conv_b, out);

    gn_kernel<<<(BB * OCC * WW * HH / 4) / 256, 256>>>(out, gn_gamma, gn_beta);
}